// round 1
// baseline (speedup 1.0000x reference)
#include <cuda_runtime.h>

// LearnableShiftViews: out[v,b,c,h,w] = separable bilinear resample of x[b,c]
// at pix = (idx + d)*size/(size-1) - 0.5 per axis, zero padding.
//
// Strategy: one block per (bc, 8-row y-tile). Stage the union of input rows
// needed by ALL 5 views into shared memory once (<=16 rows, ~12 typical),
// then compute all 5 views' outputs for the tile. Coefficients computed
// inline on ALU/FMA pipes; data path is 4 conflict-free LDS per output;
// stores are fully coalesced scalar STG (224 = 7 warps-wide exactly).

namespace {

constexpr int H = 224;
constexpr int W = 224;
constexpr int B = 64;
constexpr int C = 3;
constexpr int BCN = B * C;   // 192
constexpr int V = 5;
constexpr int TILE_Y = 8;
constexpr int ROWS_CAP = 16;
constexpr int NTHREADS = 256;

__global__ __launch_bounds__(NTHREADS)
void shift_views_kernel(const float* __restrict__ x,
                        const float* __restrict__ offs,
                        float* __restrict__ out) {
    __shared__ float srows[ROWS_CAP][W];

    const int yb  = blockIdx.x * TILE_Y;
    const int bc  = blockIdx.y;
    const int tid = threadIdx.x;

    const float sy = (float)H / (float)(H - 1);
    const float sx = (float)W / (float)(W - 1);

    // ---- Row range needed across all views (computed redundantly per thread;
    // ~40 cheap ops). i0 is monotone in y, so endpoints suffice.
    int rmin = H - 1, rmax = 0;
#pragma unroll
    for (int v = 0; v < V; ++v) {
        float dy = __ldg(&offs[2 * v]);
        int lo = (int)floorf(((float)yb + dy) * sy - 0.5f);
        int hi = (int)floorf(((float)(yb + TILE_Y - 1) + dy) * sy - 0.5f) + 1;
        lo = max(lo, 0);
        hi = min(hi, H - 1);
        rmin = min(rmin, lo);
        rmax = max(rmax, hi);
    }
    if (rmin > rmax) { rmin = 0; rmax = 0; }            // degenerate safety
    rmax = min(rmax, rmin + ROWS_CAP - 1);              // capacity clamp
    const int nrows = rmax - rmin + 1;

    // ---- Stage input rows (float4, coalesced).
    {
        const float* src = x + (size_t)bc * (H * W) + (size_t)rmin * W;
        const int total4 = nrows * (W / 4);
        for (int i = tid; i < total4; i += NTHREADS) {
            int r = i / (W / 4);
            int c = i - r * (W / 4);
            reinterpret_cast<float4*>(&srows[r][0])[c] =
                reinterpret_cast<const float4*>(src + r * W)[c];
        }
    }
    __syncthreads();

    // ---- Compute: warp ty owns output row yb+ty; lanes sweep x in 7 strides.
    const int ty   = tid >> 5;          // 0..7 (warp-uniform)
    const int lane = tid & 31;
    const int y    = yb + ty;
    const float yf = (float)y;

#pragma unroll
    for (int v = 0; v < V; ++v) {
        const float dy = __ldg(&offs[2 * v]);
        const float dx = __ldg(&offs[2 * v + 1]);

        // y-axis blend coefficients (warp-uniform, amortized over 7 x-iters)
        float ypix = (yf + dy) * sy - 0.5f;
        float py   = floorf(ypix);
        float fy   = ypix - py;
        int   iy0  = (int)py;
        float wy0  = ((unsigned)iy0       < (unsigned)H) ? (1.0f - fy) : 0.0f;
        float wy1  = ((unsigned)(iy0 + 1) < (unsigned)H) ? fy          : 0.0f;
        int r0 = min(max(iy0,     rmin), rmax) - rmin;
        int r1 = min(max(iy0 + 1, rmin), rmax) - rmin;
        const float* __restrict__ row0 = srows[r0];
        const float* __restrict__ row1 = srows[r1];

        const float cxv = dx * sx - 0.5f;
        float* __restrict__ orow =
            out + (((size_t)(v * BCN + bc)) * H + y) * W;

#pragma unroll
        for (int xi = 0; xi < W / 32; ++xi) {
            int   xx   = xi * 32 + lane;
            float xpix = fmaf((float)xx, sx, cxv);
            float px   = floorf(xpix);
            float fx   = xpix - px;
            int   ix0  = (int)px;
            float xw0  = ((unsigned)ix0       < (unsigned)W) ? (1.0f - fx) : 0.0f;
            float xw1  = ((unsigned)(ix0 + 1) < (unsigned)W) ? fx          : 0.0f;
            int c0 = min(max(ix0,     0), W - 1);
            int c1 = min(max(ix0 + 1, 0), W - 1);
            // conflict-free: lane-monotonic stride-1 smem addresses
            float t0 = row0[c0] * xw0 + row0[c1] * xw1;
            float t1 = row1[c0] * xw0 + row1[c1] * xw1;
            orow[xx] = t0 * wy0 + t1 * wy1;   // coalesced 128B/warp
        }
    }
}

}  // namespace

extern "C" void kernel_launch(void* const* d_in, const int* in_sizes, int n_in,
                              void* d_out, int out_size) {
    const float* x    = (const float*)d_in[0];
    const float* offs = (const float*)d_in[1];
    // Safety: tolerate swapped metadata order (offsets tensor has 10 elements).
    if (n_in >= 2 && in_sizes[0] == 2 * V) {
        const float* t = x; x = offs; offs = t;
    }
    dim3 grid(H / TILE_Y, BCN);
    shift_views_kernel<<<grid, NTHREADS>>>(x, offs, (float*)d_out);
}

// round 2
// speedup vs baseline: 1.1369x; 1.1369x over previous
#include <cuda_runtime.h>

// LearnableShiftViews: out[v,b,c,h,w] = separable bilinear resample of x[b,c]
// at pix = (idx + d)*size/(size-1) - 0.5 per axis, zero padding.
//
// R2: x-axis coefficients {fx, tap byte-offset} precomputed once per (v,x)
// into a global table by a tiny prologue kernel (they are invariant across
// all 192 planes and 224 rows). Shared-memory input rows are staged with
// 2 zero-pad columns on each side so the x-blend needs NO masks/clamps:
// taps for ix0 in [-1,223] land on pad-zeros exactly where the reference
// masks them, and fully out-of-range entries point both taps at pads.
// Hot loop per output: 1 LDG.64 (coeff, L1-hot) + 2 IADD + 4 LDS + 6 FP + 1 STG.

namespace {

constexpr int H = 224;
constexpr int W = 224;
constexpr int B = 64;
constexpr int C = 3;
constexpr int BCN = B * C;   // 192
constexpr int V = 5;
constexpr int TILE_Y = 8;
constexpr int ROWS_CAP = 16;
constexpr int NTHREADS = 256;
constexpr int RS = 228;      // padded row stride: [0,1]=pad0, [2..225]=data, [226,227]=pad0

// x-coefficient table: {fx, __int_as_float(byte offset of left tap in padded row)}
__device__ float2 g_xtab[V][W];

__global__ void build_xtab_kernel(const float* __restrict__ offs) {
    const int v = blockIdx.x;
    const int x = threadIdx.x;
    if (v >= V || x >= W) return;
    const float sx = (float)W / (float)(W - 1);
    const float dx = offs[2 * v + 1];
    float xpix = ((float)x + dx) * sx - 0.5f;
    float px   = floorf(xpix);
    int   ix0  = (int)px;
    float fx   = xpix - px;
    int p0;
    if (ix0 < -1 || ix0 > W - 1) { p0 = 0; fx = 0.0f; }  // both taps -> pads -> exact 0
    else                         { p0 = ix0 + 2; }       // pads absorb edge masking
    float2 e;
    e.x = fx;
    e.y = __int_as_float(p0 * 4);
    g_xtab[v][x] = e;
}

__global__ __launch_bounds__(NTHREADS)
void shift_views_kernel(const float* __restrict__ x,
                        const float* __restrict__ offs,
                        float* __restrict__ out) {
    __shared__ float srows[ROWS_CAP * RS];

    const int yb  = blockIdx.x * TILE_Y;
    const int bc  = blockIdx.y;
    const int tid = threadIdx.x;
    const float sy = (float)H / (float)(H - 1);

    // ---- Row range needed across all views (endpoints suffice; monotone).
    int rmin = H - 1, rmax = 0;
#pragma unroll
    for (int v = 0; v < V; ++v) {
        float dy = __ldg(&offs[2 * v]);
        int lo = (int)floorf(((float)yb + dy) * sy - 0.5f);
        int hi = (int)floorf(((float)(yb + TILE_Y - 1) + dy) * sy - 0.5f) + 1;
        lo = max(lo, 0);
        hi = min(hi, H - 1);
        rmin = min(rmin, lo);
        rmax = max(rmax, hi);
    }
    if (rmin > rmax) { rmin = 0; rmax = 0; }
    rmax = min(rmax, rmin + ROWS_CAP - 1);
    const int nrows = rmax - rmin + 1;

    // ---- Zero the 4 pad columns of every row (threads 0..63, one pad each).
    if (tid < ROWS_CAP * 4) {
        int r = tid >> 2, c = tid & 3;
        srows[r * RS + (c < 2 ? c : 224 + c)] = 0.0f;   // cols 0,1,226,227
    }

    // ---- Stage input rows into padded smem (float2: dst is 8B-aligned).
    {
        const float2* src = reinterpret_cast<const float2*>(
            x + (size_t)bc * (H * W) + (size_t)rmin * W);
        const int n2 = nrows * (W / 2);
        for (int i = tid; i < n2; i += NTHREADS) {
            int r = i / (W / 2);
            int c = i - r * (W / 2);
            reinterpret_cast<float2*>(&srows[r * RS + 2])[c] = src[r * (W / 2) + c];
        }
    }
    __syncthreads();

    // ---- Compute: warp ty owns output row yb+ty; lanes sweep x in 7 strides.
    const int ty   = tid >> 5;
    const int lane = tid & 31;
    const int y    = yb + ty;
    const float yf = (float)y;

#pragma unroll
    for (int v = 0; v < V; ++v) {
        const float dy = __ldg(&offs[2 * v]);

        // y-axis blend (warp-uniform, amortized over 7 x-iterations)
        float ypix = (yf + dy) * sy - 0.5f;
        float py   = floorf(ypix);
        float fy   = ypix - py;
        int   iy0  = (int)py;
        float wy0  = ((unsigned)iy0       < (unsigned)H) ? (1.0f - fy) : 0.0f;
        float wy1  = ((unsigned)(iy0 + 1) < (unsigned)H) ? fy          : 0.0f;
        int r0 = min(max(iy0,     rmin), rmax) - rmin;
        int r1 = min(max(iy0 + 1, rmin), rmax) - rmin;
        const char* row0 = (const char*)&srows[r0 * RS];
        const char* row1 = (const char*)&srows[r1 * RS];

        float* __restrict__ orow =
            out + (((size_t)(v * BCN + bc)) * H + y) * W;
        const float2* __restrict__ tab = &g_xtab[v][0];

#pragma unroll
        for (int xi = 0; xi < W / 32; ++xi) {
            int    xx  = xi * 32 + lane;
            float2 e   = __ldg(&tab[xx]);                 // {fx, byteoff} — L1-hot
            int    off = __float_as_int(e.y);
            const float* p0 = (const float*)(row0 + off); // left/right taps adjacent
            const float* p1 = (const float*)(row1 + off);
            float a0 = p0[0], a1 = p0[1];
            float b0 = p1[0], b1 = p1[1];
            float t0 = fmaf(e.x, a1 - a0, a0);            // mask-free lerp (pads=0)
            float t1 = fmaf(e.x, b1 - b0, b0);
            orow[xx] = fmaf(t1, wy1, t0 * wy0);           // coalesced 128B/warp
        }
    }
}

}  // namespace

extern "C" void kernel_launch(void* const* d_in, const int* in_sizes, int n_in,
                              void* d_out, int out_size) {
    const float* x    = (const float*)d_in[0];
    const float* offs = (const float*)d_in[1];
    if (n_in >= 2 && in_sizes[0] == 2 * V) {   // tolerate swapped metadata order
        const float* t = x; x = offs; offs = t;
    }
    build_xtab_kernel<<<V, W>>>(offs);
    dim3 grid(H / TILE_Y, BCN);
    shift_views_kernel<<<grid, NTHREADS>>>(x, offs, (float*)d_out);
}

// round 3
// speedup vs baseline: 1.2513x; 1.1006x over previous
#include <cuda_runtime.h>

// LearnableShiftViews: out[v,b,c,h,w] = separable bilinear resample of x[b,c]
// at pix = (idx + d)*size/(size-1) - 0.5 per axis, zero padding.
//
// R3: kernel is L1tex-wavefront bound (84.7% in R2). Remove the per-output
// coefficient LDG.64 (2 of ~8 wavefronts/warp-group) by computing ix0/fx
// inline on the idle FMA/ALU pipes (19-23% busy). The 2-column zero pads on
// each side of every staged smem row make the x-blend completely mask-free:
// for ix0 in [-1,223] the taps land on pad zeros exactly where the reference
// masks them; clamping p0 to [0,226] handles fully out-of-range coords
// (both taps on pads -> exact 0). Hot loop per output:
//   F2I.FLOOR + I2F + FADD(fx) + 2 IMNMX + addr math + 4 LDS.32 + 6 FP + STG.

namespace {

constexpr int H = 224;
constexpr int W = 224;
constexpr int B = 64;
constexpr int C = 3;
constexpr int BCN = B * C;   // 192
constexpr int V = 5;
constexpr int TILE_Y = 8;
constexpr int ROWS_CAP = 16;
constexpr int NTHREADS = 256;
constexpr int RS = 228;      // [0,1]=pad0, [2..225]=data, [226,227]=pad0

__global__ __launch_bounds__(NTHREADS)
void shift_views_kernel(const float* __restrict__ x,
                        const float* __restrict__ offs,
                        float* __restrict__ out) {
    __shared__ float srows[ROWS_CAP * RS];

    const int yb  = blockIdx.x * TILE_Y;
    const int bc  = blockIdx.y;
    const int tid = threadIdx.x;
    const float sy = (float)H / (float)(H - 1);
    const float sx = (float)W / (float)(W - 1);

    // ---- Row range needed across all views (endpoints suffice; monotone).
    int rmin = H - 1, rmax = 0;
#pragma unroll
    for (int v = 0; v < V; ++v) {
        float dy = __ldg(&offs[2 * v]);
        int lo = (int)floorf(((float)yb + dy) * sy - 0.5f);
        int hi = (int)floorf(((float)(yb + TILE_Y - 1) + dy) * sy - 0.5f) + 1;
        lo = max(lo, 0);
        hi = min(hi, H - 1);
        rmin = min(rmin, lo);
        rmax = max(rmax, hi);
    }
    if (rmin > rmax) { rmin = 0; rmax = 0; }
    rmax = min(rmax, rmin + ROWS_CAP - 1);
    const int nrows = rmax - rmin + 1;

    // ---- Zero the 4 pad columns of every row (threads 0..63).
    if (tid < ROWS_CAP * 4) {
        int r = tid >> 2, c = tid & 3;
        srows[r * RS + (c < 2 ? c : 224 + c)] = 0.0f;   // cols 0,1,226,227
    }

    // ---- Stage input rows into padded smem (float2, coalesced).
    {
        const float2* src = reinterpret_cast<const float2*>(
            x + (size_t)bc * (H * W) + (size_t)rmin * W);
        const int n2 = nrows * (W / 2);
        for (int i = tid; i < n2; i += NTHREADS) {
            int r = i / (W / 2);
            int c = i - r * (W / 2);
            reinterpret_cast<float2*>(&srows[r * RS + 2])[c] = src[r * (W / 2) + c];
        }
    }
    __syncthreads();

    // ---- Compute: warp ty owns output row yb+ty; lanes sweep x in 7 strides.
    const int ty   = tid >> 5;
    const int lane = tid & 31;
    const int y    = yb + ty;
    const float yf     = (float)y;
    const float lanef  = (float)lane;
    const float xstep  = 32.0f * sx;

#pragma unroll 1
    for (int v = 0; v < V; ++v) {
        const float dy = __ldg(&offs[2 * v]);
        const float dx = __ldg(&offs[2 * v + 1]);

        // y-axis blend (warp-uniform, amortized over 7 x-iterations)
        float ypix = (yf + dy) * sy - 0.5f;
        float py   = floorf(ypix);
        float fy   = ypix - py;
        int   iy0  = (int)py;
        float wy0  = ((unsigned)iy0       < (unsigned)H) ? (1.0f - fy) : 0.0f;
        float wy1  = ((unsigned)(iy0 + 1) < (unsigned)H) ? fy          : 0.0f;
        int r0 = min(max(iy0,     rmin), rmax) - rmin;
        int r1 = min(max(iy0 + 1, rmin), rmax) - rmin;
        const float* __restrict__ row0 = &srows[r0 * RS];
        const float* __restrict__ row1 = &srows[r1 * RS];

        float* __restrict__ orow =
            out + (((size_t)(v * BCN + bc)) * H + y) * W;

        // x sample position, advanced incrementally (1 FADD per iter)
        float xpix = fmaf(lanef, sx, dx * sx - 0.5f);

#pragma unroll
        for (int xi = 0; xi < W / 32; ++xi) {
            int   ix0 = __float2int_rd(xpix);            // floor
            float fx  = xpix - __int2float_rn(ix0);      // exact for small ints
            int   p0  = min(max(ix0 + 2, 0), RS - 2);    // pads absorb edges
            float a0 = row0[p0], a1 = row0[p0 + 1];
            float b0 = row1[p0], b1 = row1[p0 + 1];
            float t0 = fmaf(fx, a1 - a0, a0);            // mask-free lerp
            float t1 = fmaf(fx, b1 - b0, b0);
            orow[xi * 32 + lane] = fmaf(t1, wy1, t0 * wy0);  // coalesced
            xpix += xstep;
        }
    }
}

}  // namespace

extern "C" void kernel_launch(void* const* d_in, const int* in_sizes, int n_in,
                              void* d_out, int out_size) {
    const float* x    = (const float*)d_in[0];
    const float* offs = (const float*)d_in[1];
    if (n_in >= 2 && in_sizes[0] == 2 * V) {   // tolerate swapped metadata order
        const float* t = x; x = offs; offs = t;
    }
    dim3 grid(H / TILE_Y, BCN);
    shift_views_kernel<<<grid, NTHREADS>>>(x, offs, (float*)d_out);
}